// round 6
// baseline (speedup 1.0000x reference)
#include <cuda_runtime.h>
#include <cstdint>

// ---------------------------------------------------------------------------
// SpikingOpticalFlowBranch — fused flow-diff + conv3x3(2->64) + LIF scan.
// R6: packed fma.rn.f32x2 halves the FMA-pipe instruction count (the measured
// bottleneck). V carried as 32 x f32x2 register pairs; weights consumed as
// ulonglong2 from shared (no repack); spike phase unpacks pairs for free.
// Output layout: [0,160) readout, [160,3200) logits (t-major), [3200] sr.
// ---------------------------------------------------------------------------

#define T_STEPS 19
#define BATCH   16
#define HH      128
#define WW      128
#define NCH     64
#define OUTD    10
#define THR_F   1.0f
#define HALO    18
#define FRAME_ELEMS (HALO*HALO*2)   // 648

__device__ int g_chsum[T_STEPS * BATCH * NCH];

// packed f32x2 helpers -------------------------------------------------------
__device__ __forceinline__ unsigned long long fma2(unsigned long long a,
                                                   unsigned long long b,
                                                   unsigned long long c) {
    unsigned long long d;
    asm("fma.rn.f32x2 %0, %1, %2, %3;" : "=l"(d) : "l"(a), "l"(b), "l"(c));
    return d;
}
__device__ __forceinline__ unsigned long long pack2(float lo, float hi) {
    unsigned long long d;
    asm("mov.b64 %0, {%1, %2};" : "=l"(d) : "f"(lo), "f"(hi));
    return d;
}

// ---------------------------------------------------------------------------
__global__ void zero_chsum_kernel() {
    int i = blockIdx.x * blockDim.x + threadIdx.x;
    if (i < T_STEPS * BATCH * NCH) g_chsum[i] = 0;
}

// ---------------------------------------------------------------------------
// Main kernel: 1024 blocks x 256 threads, one pixel per thread, V[64] packed
// into 32 register pairs carried across all 19 steps.
// ---------------------------------------------------------------------------
__global__ __launch_bounds__(256, 2)
void lif_main_kernel(const float* __restrict__ x,
                     const float* __restrict__ wconv,
                     const float* __restrict__ bconv) {
    __shared__ float               frame_s[2][FRAME_ELEMS];
    __shared__ float               flow_s[FRAME_ELEMS];
    __shared__ ulonglong2          ws2[18 * 16];   // [tap][4ch-group] = 4608 B
    __shared__ unsigned long long  bs2[32];        // bias pairs
    __shared__ int                 chsum_s[NCH];

    const int tid  = threadIdx.x;
    const int lane = tid & 31;
    const int b    = blockIdx.x >> 6;
    const int tile = blockIdx.x & 63;
    const int th0  = (tile >> 3) << 4;
    const int tw0  = (tile & 7) << 4;
    const int ty   = tid >> 4;
    const int tx   = tid & 15;

    // weights: global [ky][kx][ci][co] == [tap 0..17][co 0..63] -> same bytes
    {
        float* wsf = reinterpret_cast<float*>(ws2);
        for (int i = tid; i < 18 * NCH; i += 256) wsf[i] = wconv[i];
        if (tid < NCH) reinterpret_cast<float*>(bs2)[tid] = bconv[tid];
    }

    auto load_frame = [&](int t, float* dst) {
        const float* xt = x + ((size_t)t * BATCH + b) * (HH * WW * 2);
        for (int i = tid; i < FRAME_ELEMS; i += 256) {
            int row = i / (HALO * 2);
            int rem = i - row * (HALO * 2);
            int col = rem >> 1;
            int c   = rem & 1;
            int gh  = th0 + row - 1;
            int gw  = tw0 + col - 1;
            float v = 0.0f;
            if ((unsigned)gh < (unsigned)HH && (unsigned)gw < (unsigned)WW)
                v = xt[(gh * WW + gw) * 2 + c];
            dst[i] = v;
        }
    };

    load_frame(0, frame_s[0]);

    const unsigned long long BETA2 = pack2(0.9f, 0.9f);

    unsigned long long V2[32];
#pragma unroll
    for (int i = 0; i < 32; i++) V2[i] = 0ull;

#pragma unroll 1
    for (int t = 0; t < T_STEPS; t++) {
        if (tid < NCH) chsum_s[tid] = 0;
        load_frame(t + 1, frame_s[(t + 1) & 1]);
        __syncthreads();

        {   // flow tile
            const float* fc = frame_s[(t + 1) & 1];
            const float* fp = frame_s[t & 1];
            for (int i = tid; i < FRAME_ELEMS; i += 256) flow_s[i] = fc[i] - fp[i];
        }
        __syncthreads();

        // gather 9 spatial taps (each = 2 contiguous input channels)
        float2 fp9[9];
#pragma unroll
        for (int dy = 0; dy < 3; dy++)
#pragma unroll
            for (int dx = 0; dx < 3; dx++)
                fp9[dy * 3 + dx] =
                    *reinterpret_cast<const float2*>(&flow_s[((ty + dy) * HALO + (tx + dx)) * 2]);

        // V = beta*V + bias
#pragma unroll
        for (int i = 0; i < 32; i++) V2[i] = fma2(V2[i], BETA2, bs2[i]);

        // V += f[tap] * w[tap][:]   (packed pairs of output channels)
#pragma unroll
        for (int pos = 0; pos < 9; pos++) {
            unsigned long long fa = pack2(fp9[pos].x, fp9[pos].x);
            unsigned long long fb = pack2(fp9[pos].y, fp9[pos].y);
#pragma unroll
            for (int j = 0; j < 16; j++) {
                ulonglong2 w = ws2[(pos * 2 + 0) * 16 + j];
                V2[2 * j + 0] = fma2(fa, w.x, V2[2 * j + 0]);
                V2[2 * j + 1] = fma2(fa, w.y, V2[2 * j + 1]);
            }
#pragma unroll
            for (int j = 0; j < 16; j++) {
                ulonglong2 w = ws2[(pos * 2 + 1) * 16 + j];
                V2[2 * j + 0] = fma2(fb, w.x, V2[2 * j + 0]);
                V2[2 * j + 1] = fma2(fb, w.y, V2[2 * j + 1]);
            }
        }

        // spike + soft reset + ballot counting (unpack pairs: free reg aliases)
        int acc0 = 0, acc1 = 0;
#pragma unroll
        for (int i = 0; i < 32; i++) {
            unsigned long long v = V2[i];
            float lo = __uint_as_float((unsigned)v);
            float hi = __uint_as_float((unsigned)(v >> 32));
            bool s0 = lo > THR_F;
            bool s1 = hi > THR_F;
            unsigned m0 = __ballot_sync(0xffffffffu, s0);
            unsigned m1 = __ballot_sync(0xffffffffu, s1);
            if (s0) lo -= THR_F;
            if (s1) hi -= THR_F;
            V2[i] = pack2(lo, hi);
            int ch0 = 2 * i, ch1 = 2 * i + 1;
            if (ch0 < 32) {
                if (lane == ch0) acc0 += __popc(m0);
                if (lane == ch1) acc0 += __popc(m1);
            } else {
                if (lane == ch0 - 32) acc1 += __popc(m0);
                if (lane == ch1 - 32) acc1 += __popc(m1);
            }
        }
        atomicAdd(&chsum_s[lane],      acc0);
        atomicAdd(&chsum_s[lane + 32], acc1);
        __syncthreads();

        if (tid < NCH)
            atomicAdd(&g_chsum[(t * BATCH + b) * NCH + tid], chsum_s[tid]);
    }
}

// ---------------------------------------------------------------------------
// Merged epilogue: logits, readout, spike-rate. One block, 320 threads.
// ---------------------------------------------------------------------------
__global__ void epilogue_kernel(const float* __restrict__ w_head,
                                const float* __restrict__ b_head,
                                float* __restrict__ out) {
    __shared__ long long part[320];
    int tid = threadIdx.x;

    // logits[t][b][:] from integer counts (cnt/2^14 exact in fp32)
    if (tid < T_STEPS * BATCH) {
        const int* cs = g_chsum + tid * NCH;
        float acc[OUTD];
#pragma unroll
        for (int o = 0; o < OUTD; o++) acc[o] = b_head[o];
        for (int ch = 0; ch < NCH; ch++) {
            float ms = (float)cs[ch] * (1.0f / 16384.0f);
#pragma unroll
            for (int o = 0; o < OUTD; o++) acc[o] += ms * w_head[ch * OUTD + o];
        }
#pragma unroll
        for (int o = 0; o < OUTD; o++) out[160 + tid * OUTD + o] = acc[o];
    }
    __syncthreads();

    // readout = mean_t logits
    if (tid < BATCH * OUTD) {
        int b = tid / OUTD, o = tid % OUTD;
        float s = 0.0f;
        for (int t = 0; t < T_STEPS; t++)
            s += out[160 + (t * BATCH + b) * OUTD + o];
        out[b * OUTD + o] = s * (1.0f / (float)T_STEPS);
    }

    // sr = total spikes / (19*16*128*128*64)
    long long tot = 0;
    for (int i = tid; i < T_STEPS * BATCH * NCH; i += 320) tot += (long long)g_chsum[i];
    part[tid] = tot;
    __syncthreads();
    if (tid < 64)
        part[tid] = part[tid] + part[tid + 64] + part[tid + 128] +
                    part[tid + 192] + part[tid + 256];
    __syncthreads();
    for (int s = 32; s > 0; s >>= 1) {
        if (tid < s) part[tid] += part[tid + s];
        __syncthreads();
    }
    if (tid == 0)
        out[3200] = (float)((double)part[0] / 318767104.0);
}

// ---------------------------------------------------------------------------
extern "C" void kernel_launch(void* const* d_in, const int* in_sizes, int n_in,
                              void* d_out, int out_size) {
    const float* x     = (const float*)d_in[0];   // [20,16,128,128,2]
    const float* wconv = (const float*)d_in[1];   // [3,3,2,64]
    const float* bconv = (const float*)d_in[2];   // [64]
    const float* whead = (const float*)d_in[3];   // [64,10]
    const float* bhead = (const float*)d_in[4];   // [10]
    float* out = (float*)d_out;                   // 3201 floats

    zero_chsum_kernel<<<76, 256>>>();
    lif_main_kernel<<<BATCH * 64, 256>>>(x, wconv, bconv);
    epilogue_kernel<<<1, 320>>>(whead, bhead, out);
}

// round 7
// speedup vs baseline: 1.4693x; 1.4693x over previous
#include <cuda_runtime.h>
#include <cstdint>

// ---------------------------------------------------------------------------
// SpikingOpticalFlowBranch — fused flow-diff + conv3x3(2->64) + LIF scan.
// R7: fma.rn.f32x2 retained (R6 proved it bit-exact) but register pressure
// fixed: 512 threads/block, thread = 1 pixel x 32 channels -> V = 16 pairs
// (32 regs). Flow tile stored pre-duplicated as packed f32x2 so tap operands
// need no per-use packing. Weight pairs consumed via ulonglong2 reinterpret.
// Output layout: [0,160) readout, [160,3200) logits (t-major), [3200] sr.
// ---------------------------------------------------------------------------

#define T_STEPS 19
#define BATCH   16
#define HH      128
#define WW      128
#define NCH     64
#define OUTD    10
#define THR_F   1.0f
#define HALO    18
#define FRAME_ELEMS (HALO*HALO*2)   // 648

__device__ int g_chsum[T_STEPS * BATCH * NCH];

// packed f32x2 helpers -------------------------------------------------------
__device__ __forceinline__ unsigned long long fma2(unsigned long long a,
                                                   unsigned long long b,
                                                   unsigned long long c) {
    unsigned long long d;
    asm("fma.rn.f32x2 %0, %1, %2, %3;" : "=l"(d) : "l"(a), "l"(b), "l"(c));
    return d;
}
__device__ __forceinline__ unsigned long long pack2(float lo, float hi) {
    unsigned long long d;
    asm("mov.b64 %0, {%1, %2};" : "=l"(d) : "f"(lo), "f"(hi));
    return d;
}

// ---------------------------------------------------------------------------
__global__ void zero_chsum_kernel() {
    int i = blockIdx.x * blockDim.x + threadIdx.x;
    if (i < T_STEPS * BATCH * NCH) g_chsum[i] = 0;
}

// ---------------------------------------------------------------------------
// Main kernel: 1024 blocks x 512 threads.
//   warps 0-7  -> channels [0,32)   of their pixel
//   warps 8-15 -> channels [32,64)  of their pixel
// Each thread carries 16 f32x2 pairs of V across all 19 steps.
// ---------------------------------------------------------------------------
__global__ __launch_bounds__(512)
void lif_main_kernel(const float* __restrict__ x,
                     const float* __restrict__ wconv,
                     const float* __restrict__ bconv) {
    __shared__ float                            frame_s[2][FRAME_ELEMS];
    __shared__ __align__(16) unsigned long long flow_d[FRAME_ELEMS];  // dup pairs
    __shared__ __align__(16) unsigned long long ws8[18 * 32];         // [tap][pair]
    __shared__ unsigned long long               bs8[32];
    __shared__ int                              chsum_s[NCH];

    const int tid  = threadIdx.x;
    const int lane = tid & 31;
    const int pix  = tid & 255;
    const int h    = tid >> 8;          // channel half: 0 -> ch[0,32), 1 -> ch[32,64)
    const int ty   = pix >> 4;
    const int tx   = pix & 15;
    const int b    = blockIdx.x >> 6;
    const int tile = blockIdx.x & 63;
    const int th0  = (tile >> 3) << 4;
    const int tw0  = (tile & 7) << 4;

    // weights: global [ky][kx][ci][co] == [tap 0..17][co 0..63]; pairs = adjacent co
    {
        float* wsf = reinterpret_cast<float*>(ws8);
        for (int i = tid; i < 18 * NCH; i += 512) wsf[i] = wconv[i];
        if (tid < NCH) reinterpret_cast<float*>(bs8)[tid] = bconv[tid];
    }

    auto load_frame = [&](int t, float* dst) {
        const float* xt = x + ((size_t)t * BATCH + b) * (HH * WW * 2);
        for (int i = tid; i < FRAME_ELEMS; i += 512) {
            int row = i / (HALO * 2);
            int rem = i - row * (HALO * 2);
            int col = rem >> 1;
            int c   = rem & 1;
            int gh  = th0 + row - 1;
            int gw  = tw0 + col - 1;
            float v = 0.0f;
            if ((unsigned)gh < (unsigned)HH && (unsigned)gw < (unsigned)WW)
                v = xt[(gh * WW + gw) * 2 + c];
            dst[i] = v;
        }
    };

    load_frame(0, frame_s[0]);

    const unsigned long long BETA2 = pack2(0.9f, 0.9f);

    unsigned long long V2[16];
#pragma unroll
    for (int i = 0; i < 16; i++) V2[i] = 0ull;

#pragma unroll 1
    for (int t = 0; t < T_STEPS; t++) {
        if (tid < NCH) chsum_s[tid] = 0;
        load_frame(t + 1, frame_s[(t + 1) & 1]);
        __syncthreads();

        {   // flow tile, each element stored as duplicated f32x2 pair
            const float* fc = frame_s[(t + 1) & 1];
            const float* fp = frame_s[t & 1];
            for (int i = tid; i < FRAME_ELEMS; i += 512) {
                float d = fc[i] - fp[i];
                flow_d[i] = pack2(d, d);
            }
        }
        __syncthreads();

        // V = beta*V + bias
#pragma unroll
        for (int i = 0; i < 16; i++) V2[i] = fma2(V2[i], BETA2, bs8[h * 16 + i]);

        // conv: 9 spatial taps x 2 input channels, 32 output channels (16 pairs)
#pragma unroll
        for (int pos = 0; pos < 9; pos++) {
            const int dy = pos / 3, dx = pos % 3;
            // both input-channel taps for this position, pre-duplicated pairs
            ulonglong2 tp = *reinterpret_cast<const ulonglong2*>(
                &flow_d[((ty + dy) * HALO + (tx + dx)) * 2]);
            const ulonglong2* wA = reinterpret_cast<const ulonglong2*>(
                ws8 + (2 * pos + 0) * 32 + h * 16);
            const ulonglong2* wB = reinterpret_cast<const ulonglong2*>(
                ws8 + (2 * pos + 1) * 32 + h * 16);
#pragma unroll
            for (int j = 0; j < 8; j++) {
                ulonglong2 wa = wA[j];
                V2[2 * j + 0] = fma2(tp.x, wa.x, V2[2 * j + 0]);
                V2[2 * j + 1] = fma2(tp.x, wa.y, V2[2 * j + 1]);
            }
#pragma unroll
            for (int j = 0; j < 8; j++) {
                ulonglong2 wb = wB[j];
                V2[2 * j + 0] = fma2(tp.y, wb.x, V2[2 * j + 0]);
                V2[2 * j + 1] = fma2(tp.y, wb.y, V2[2 * j + 1]);
            }
        }

        // spike + soft reset + ballot counting
        // warp = 32 pixels of one channel-half; lane L owns count of channel 2i(+1)
        int acc = 0;
#pragma unroll
        for (int i = 0; i < 16; i++) {
            unsigned long long v = V2[i];
            float lo = __uint_as_float((unsigned)v);
            float hi = __uint_as_float((unsigned)(v >> 32));
            bool s0 = lo > THR_F;
            bool s1 = hi > THR_F;
            unsigned m0 = __ballot_sync(0xffffffffu, s0);
            unsigned m1 = __ballot_sync(0xffffffffu, s1);
            if (s0) lo -= THR_F;
            if (s1) hi -= THR_F;
            V2[i] = pack2(lo, hi);
            if (lane == 2 * i)     acc += __popc(m0);
            if (lane == 2 * i + 1) acc += __popc(m1);
        }
        atomicAdd(&chsum_s[h * 32 + lane], acc);
        __syncthreads();

        if (tid < NCH)
            atomicAdd(&g_chsum[(t * BATCH + b) * NCH + tid], chsum_s[tid]);
    }
}

// ---------------------------------------------------------------------------
// Merged epilogue: logits, readout, spike-rate. One block, 320 threads.
// ---------------------------------------------------------------------------
__global__ void epilogue_kernel(const float* __restrict__ w_head,
                                const float* __restrict__ b_head,
                                float* __restrict__ out) {
    __shared__ long long part[320];
    int tid = threadIdx.x;

    // logits[t][b][:] from integer counts (cnt/2^14 exact in fp32)
    if (tid < T_STEPS * BATCH) {
        const int* cs = g_chsum + tid * NCH;
        float acc[OUTD];
#pragma unroll
        for (int o = 0; o < OUTD; o++) acc[o] = b_head[o];
        for (int ch = 0; ch < NCH; ch++) {
            float ms = (float)cs[ch] * (1.0f / 16384.0f);
#pragma unroll
            for (int o = 0; o < OUTD; o++) acc[o] += ms * w_head[ch * OUTD + o];
        }
#pragma unroll
        for (int o = 0; o < OUTD; o++) out[160 + tid * OUTD + o] = acc[o];
    }
    __syncthreads();

    // readout = mean_t logits
    if (tid < BATCH * OUTD) {
        int b = tid / OUTD, o = tid % OUTD;
        float s = 0.0f;
        for (int t = 0; t < T_STEPS; t++)
            s += out[160 + (t * BATCH + b) * OUTD + o];
        out[b * OUTD + o] = s * (1.0f / (float)T_STEPS);
    }

    // sr = total spikes / (19*16*128*128*64)
    long long tot = 0;
    for (int i = tid; i < T_STEPS * BATCH * NCH; i += 320) tot += (long long)g_chsum[i];
    part[tid] = tot;
    __syncthreads();
    if (tid < 64)
        part[tid] = part[tid] + part[tid + 64] + part[tid + 128] +
                    part[tid + 192] + part[tid + 256];
    __syncthreads();
    for (int s = 32; s > 0; s >>= 1) {
        if (tid < s) part[tid] += part[tid + s];
        __syncthreads();
    }
    if (tid == 0)
        out[3200] = (float)((double)part[0] / 318767104.0);
}

// ---------------------------------------------------------------------------
extern "C" void kernel_launch(void* const* d_in, const int* in_sizes, int n_in,
                              void* d_out, int out_size) {
    const float* x     = (const float*)d_in[0];   // [20,16,128,128,2]
    const float* wconv = (const float*)d_in[1];   // [3,3,2,64]
    const float* bconv = (const float*)d_in[2];   // [64]
    const float* whead = (const float*)d_in[3];   // [64,10]
    const float* bhead = (const float*)d_in[4];   // [10]
    float* out = (float*)d_out;                   // 3201 floats

    zero_chsum_kernel<<<76, 256>>>();
    lif_main_kernel<<<BATCH * 64, 512>>>(x, wconv, bconv);
    epilogue_kernel<<<1, 320>>>(whead, bhead, out);
}

// round 8
// speedup vs baseline: 1.8713x; 1.2736x over previous
#include <cuda_runtime.h>
#include <cstdint>

// ---------------------------------------------------------------------------
// SpikingOpticalFlowBranch — fused flow-diff + conv3x3(2->64) + LIF scan.
// R8: scalar FFMA (f32x2 proven neutral in R6/R7). Channel-split: each CTA
// handles 32 of the 64 channels for its 16x16 pixel tile -> ~70 regs/thread,
// 3-4 CTAs/SM resident for latency hiding; grid 2048 for finer wave tail.
// g_chsum zeroed by the epilogue after use (no separate zero kernel).
// Output layout: [0,160) readout, [160,3200) logits (t-major), [3200] sr.
// ---------------------------------------------------------------------------

#define T_STEPS 19
#define BATCH   16
#define HH      128
#define WW      128
#define NCH     64
#define HCH     32          // channels per CTA
#define OUTD    10
#define BETA_F  0.9f
#define THR_F   1.0f
#define HALO    18
#define FRAME_ELEMS (HALO*HALO*2)   // 648

__device__ int g_chsum[T_STEPS * BATCH * NCH];   // static-init 0; epilogue re-zeros

// ---------------------------------------------------------------------------
// Main kernel: grid = 16 batch x 64 tiles x 2 channel-halves = 2048 blocks,
// 256 threads. Thread = one pixel, 32 channels of V in registers, 19 steps.
// ---------------------------------------------------------------------------
__global__ __launch_bounds__(256)
void lif_main_kernel(const float* __restrict__ x,
                     const float* __restrict__ wconv,
                     const float* __restrict__ bconv) {
    __shared__ float  frame_s[2][FRAME_ELEMS];   // ping-pong raw frames
    __shared__ float  flow_s[FRAME_ELEMS];       // current flow tile
    __shared__ float4 ws4[18 * 8];               // weights [tap][8 x float4] (32 ch)
    __shared__ float4 bs4[8];                    // bias (this half)
    __shared__ int    chsum_s[HCH];

    const int tid  = threadIdx.x;
    const int lane = tid & 31;
    const int hf   = blockIdx.x & 1;             // channel half
    const int tile = (blockIdx.x >> 1) & 63;
    const int b    = blockIdx.x >> 7;            // batch
    const int th0  = (tile >> 3) << 4;
    const int tw0  = (tile & 7) << 4;
    const int ty   = tid >> 4;
    const int tx   = tid & 15;

    // weights: global [ky][kx][ci][co] == [tap 0..17][co 0..63]; take our 32 co
    {
        float* wsf = reinterpret_cast<float*>(ws4);
        for (int i = tid; i < 18 * HCH; i += 256) {
            int tap = i >> 5, c = i & 31;
            wsf[i] = wconv[tap * NCH + hf * HCH + c];
        }
        if (tid < HCH) reinterpret_cast<float*>(bs4)[tid] = bconv[hf * HCH + tid];
    }

    auto load_frame = [&](int t, float* dst) {
        const float* xt = x + ((size_t)t * BATCH + b) * (HH * WW * 2);
        for (int i = tid; i < FRAME_ELEMS; i += 256) {
            int row = i / (HALO * 2);
            int rem = i - row * (HALO * 2);
            int col = rem >> 1;
            int c   = rem & 1;
            int gh  = th0 + row - 1;
            int gw  = tw0 + col - 1;
            float v = 0.0f;
            if ((unsigned)gh < (unsigned)HH && (unsigned)gw < (unsigned)WW)
                v = xt[(gh * WW + gw) * 2 + c];
            dst[i] = v;
        }
    };

    load_frame(0, frame_s[0]);

    float V[HCH];
#pragma unroll
    for (int ch = 0; ch < HCH; ch++) V[ch] = 0.0f;

#pragma unroll 1
    for (int t = 0; t < T_STEPS; t++) {
        // stage next frame + zero per-block counters
        if (tid < HCH) chsum_s[tid] = 0;
        load_frame(t + 1, frame_s[(t + 1) & 1]);
        __syncthreads();

        {   // flow tile = frame[t+1] - frame[t]
            const float* fc = frame_s[(t + 1) & 1];
            const float* fp = frame_s[t & 1];
            for (int i = tid; i < FRAME_ELEMS; i += 256) flow_s[i] = fc[i] - fp[i];
        }
        __syncthreads();

        // gather 18 taps for this pixel
        float f[18];
#pragma unroll
        for (int dy = 0; dy < 3; dy++)
#pragma unroll
            for (int dx = 0; dx < 3; dx++) {
                int base = ((ty + dy) * HALO + (tx + dx)) * 2;
                f[(dy * 3 + dx) * 2 + 0] = flow_s[base + 0];
                f[(dy * 3 + dx) * 2 + 1] = flow_s[base + 1];
            }

        // V = beta*V + bias   (same arithmetic order as R5 -> bit-identical)
#pragma unroll
        for (int c4 = 0; c4 < 8; c4++) {
            float4 bb = bs4[c4];
            V[c4 * 4 + 0] = BETA_F * V[c4 * 4 + 0] + bb.x;
            V[c4 * 4 + 1] = BETA_F * V[c4 * 4 + 1] + bb.y;
            V[c4 * 4 + 2] = BETA_F * V[c4 * 4 + 2] + bb.z;
            V[c4 * 4 + 3] = BETA_F * V[c4 * 4 + 3] + bb.w;
        }
        // V += sum_taps f[tap] * w[tap][ch]
#pragma unroll
        for (int tap = 0; tap < 18; tap++) {
            float fv = f[tap];
#pragma unroll
            for (int c4 = 0; c4 < 8; c4++) {
                float4 w = ws4[tap * 8 + c4];
                V[c4 * 4 + 0] += fv * w.x;
                V[c4 * 4 + 1] += fv * w.y;
                V[c4 * 4 + 2] += fv * w.z;
                V[c4 * 4 + 3] += fv * w.w;
            }
        }

        // spike + soft reset + warp-ballot counting (lane L owns channel L)
        int acc = 0;
#pragma unroll
        for (int ch = 0; ch < HCH; ch++) {
            bool s = V[ch] > THR_F;
            unsigned m = __ballot_sync(0xffffffffu, s);
            if (s) V[ch] -= THR_F;
            if (lane == ch) acc += __popc(m);
        }
        atomicAdd(&chsum_s[lane], acc);
        __syncthreads();

        if (tid < HCH)
            atomicAdd(&g_chsum[(t * BATCH + b) * NCH + hf * HCH + tid], chsum_s[tid]);
    }
}

// ---------------------------------------------------------------------------
// Epilogue: logits, readout, spike-rate; then zero g_chsum for the next replay.
// One block, 320 threads.
// ---------------------------------------------------------------------------
__global__ void epilogue_kernel(const float* __restrict__ w_head,
                                const float* __restrict__ b_head,
                                float* __restrict__ out) {
    __shared__ long long part[320];
    int tid = threadIdx.x;

    // logits[t][b][:] from integer counts (cnt/2^14 exact in fp32)
    if (tid < T_STEPS * BATCH) {
        const int* cs = g_chsum + tid * NCH;
        float acc[OUTD];
#pragma unroll
        for (int o = 0; o < OUTD; o++) acc[o] = b_head[o];
        for (int ch = 0; ch < NCH; ch++) {
            float ms = (float)cs[ch] * (1.0f / 16384.0f);
#pragma unroll
            for (int o = 0; o < OUTD; o++) acc[o] += ms * w_head[ch * OUTD + o];
        }
#pragma unroll
        for (int o = 0; o < OUTD; o++) out[160 + tid * OUTD + o] = acc[o];
    }

    // sr = total spikes / (19*16*128*128*64)
    long long tot = 0;
    for (int i = tid; i < T_STEPS * BATCH * NCH; i += 320) tot += (long long)g_chsum[i];
    part[tid] = tot;
    __syncthreads();

    // readout = mean_t logits (logits already in out[])
    if (tid < BATCH * OUTD) {
        int b = tid / OUTD, o = tid % OUTD;
        float s = 0.0f;
        for (int t = 0; t < T_STEPS; t++)
            s += out[160 + (t * BATCH + b) * OUTD + o];
        out[b * OUTD + o] = s * (1.0f / (float)T_STEPS);
    }

    if (tid < 64)
        part[tid] = part[tid] + part[tid + 64] + part[tid + 128] +
                    part[tid + 192] + part[tid + 256];
    __syncthreads();
    for (int s = 32; s > 0; s >>= 1) {
        if (tid < s) part[tid] += part[tid + s];
        __syncthreads();
    }
    if (tid == 0)
        out[3200] = (float)((double)part[0] / 318767104.0);

    // zero g_chsum for the next graph replay (all reads above are done)
    __syncthreads();
    for (int i = tid; i < T_STEPS * BATCH * NCH; i += 320) g_chsum[i] = 0;
}

// ---------------------------------------------------------------------------
extern "C" void kernel_launch(void* const* d_in, const int* in_sizes, int n_in,
                              void* d_out, int out_size) {
    const float* x     = (const float*)d_in[0];   // [20,16,128,128,2]
    const float* wconv = (const float*)d_in[1];   // [3,3,2,64]
    const float* bconv = (const float*)d_in[2];   // [64]
    const float* whead = (const float*)d_in[3];   // [64,10]
    const float* bhead = (const float*)d_in[4];   // [10]
    float* out = (float*)d_out;                   // 3201 floats

    lif_main_kernel<<<BATCH * 64 * 2, 256>>>(x, wconv, bconv);
    epilogue_kernel<<<1, 320>>>(whead, bhead, out);
}